// round 13
// baseline (speedup 1.0000x reference)
#include <cuda_runtime.h>
#include <cstdint>

#define SEQ   2048
#define BATCH 32
#define IDIM  256
#define HDIM  256
#define G4    1024

// 268 MB scratch for precomputed input projections: Xg[t][b][g]
__device__ float g_xg[SEQ * BATCH * G4];

__device__ __forceinline__ void ffma2(uint64_t& acc, uint64_t a, uint64_t b) {
    asm("fma.rn.f32x2 %0, %1, %2, %0;" : "+l"(acc) : "l"(a), "l"(b));
}
__device__ __forceinline__ float hsum2(uint64_t a) {
    uint32_t lo, hi;
    asm("mov.b64 {%0,%1}, %2;" : "=r"(lo), "=r"(hi) : "l"(a));
    return __uint_as_float(lo) + __uint_as_float(hi);
}

// ---------------------------------------------------------------------------
// Kernel 1 (unchanged from R12): Xg = x @ W_ih^T + b_ih + b_hh
// ---------------------------------------------------------------------------
#define BM 64
#define BN 64
#define BK 32

__global__ __launch_bounds__(256) void xproj_kernel(
    const float* __restrict__ x,
    const float* __restrict__ Wih,
    const float* __restrict__ bih,
    const float* __restrict__ bhh)
{
    __shared__ float As[BK][BM];
    __shared__ float Bs[BK][BN];

    const int tid  = threadIdx.x;
    const int mblk = blockIdx.x;
    const int nblk = blockIdx.y;

    const float* Arow = x   + (size_t)mblk * BM * IDIM;
    const float* Brow = Wih + (size_t)nblk * BN * IDIM;

    const int tx = tid & 15;
    const int ty = tid >> 4;

    uint64_t acc01[4] = {}, acc23[4] = {};

    const int lr  = tid >> 2;
    const int lkq = (tid & 3) * 8;

    for (int k0 = 0; k0 < IDIM; k0 += BK) {
        {
            float4 v0 = *(const float4*)(Arow + lr * IDIM + k0 + lkq);
            float4 v1 = *(const float4*)(Arow + lr * IDIM + k0 + lkq + 4);
            As[lkq + 0][lr] = v0.x; As[lkq + 1][lr] = v0.y;
            As[lkq + 2][lr] = v0.z; As[lkq + 3][lr] = v0.w;
            As[lkq + 4][lr] = v1.x; As[lkq + 5][lr] = v1.y;
            As[lkq + 6][lr] = v1.z; As[lkq + 7][lr] = v1.w;

            float4 w0 = *(const float4*)(Brow + lr * IDIM + k0 + lkq);
            float4 w1 = *(const float4*)(Brow + lr * IDIM + k0 + lkq + 4);
            Bs[lkq + 0][lr] = w0.x; Bs[lkq + 1][lr] = w0.y;
            Bs[lkq + 2][lr] = w0.z; Bs[lkq + 3][lr] = w0.w;
            Bs[lkq + 4][lr] = w1.x; Bs[lkq + 5][lr] = w1.y;
            Bs[lkq + 6][lr] = w1.z; Bs[lkq + 7][lr] = w1.w;
        }
        __syncthreads();

        #pragma unroll
        for (int kk = 0; kk < BK; kk++) {
            float4 av = *(const float4*)&As[kk][ty * 4];
            const uint64_t b01 = *(const uint64_t*)&Bs[kk][tx * 4];
            const uint64_t b23 = *(const uint64_t*)&Bs[kk][tx * 4 + 2];
            float a[4] = {av.x, av.y, av.z, av.w};
            #pragma unroll
            for (int i = 0; i < 4; i++) {
                uint64_t aa;
                asm("mov.b64 %0, {%1,%1};" : "=l"(aa) : "f"(a[i]));
                ffma2(acc01[i], aa, b01);
                ffma2(acc23[i], aa, b23);
            }
        }
        __syncthreads();
    }

    const int mb = mblk * BM + ty * 4;
    const int nb = nblk * BN + tx * 4;
    float bias[4];
    #pragma unroll
    for (int jj = 0; jj < 4; jj++)
        bias[jj] = bih[nb + jj] + bhh[nb + jj];

    #pragma unroll
    for (int i = 0; i < 4; i++) {
        uint32_t lo, hi, lo2, hi2;
        asm("mov.b64 {%0,%1}, %2;" : "=r"(lo), "=r"(hi) : "l"(acc01[i]));
        asm("mov.b64 {%0,%1}, %2;" : "=r"(lo2), "=r"(hi2) : "l"(acc23[i]));
        float4 v;
        v.x = __uint_as_float(lo)  + bias[0];
        v.y = __uint_as_float(hi)  + bias[1];
        v.z = __uint_as_float(lo2) + bias[2];
        v.w = __uint_as_float(hi2) + bias[3];
        *(float4*)&g_xg[(size_t)(mb + i) * G4 + nb] = v;
    }
}

// ---------------------------------------------------------------------------
// Kernel 2: dual-pair interleaved recurrence.
// 8 clusters x 8 CTAs; cluster owns 4 batches = 2 independent pairs (A, B).
// Same warp layout & SAME in-register W_hh for both pairs. Phase A then
// phase B per timestep: pair A's serial tail + DSMEM hop overlap pair B's
// k-loop. Owners: pair0 = warps 0/1 (barrier 1), pair1 = warps 2/3
// (barrier 2). Per-pair mbarriers/buffers; b64-packed st.async broadcast.
// ---------------------------------------------------------------------------
__device__ __forceinline__ void mbar_wait(uint32_t addr, unsigned par) {
    asm volatile(
        "{\n\t"
        ".reg .pred P;\n\t"
        "WAIT_%=:\n\t"
        "mbarrier.try_wait.parity.acquire.cta.shared::cta.b64 P, [%0], %1, 0x989680;\n\t"
        "@P bra DONE_%=;\n\t"
        "bra WAIT_%=;\n\t"
        "DONE_%=:\n\t"
        "}"
        :: "r"(addr), "r"(par) : "memory");
}

#define TX_PER_BUF 2048   // 8 ranks x 32 pairs x 8 B per pair-buffer

__global__ void __cluster_dims__(8, 1, 1) __launch_bounds__(512, 1)
lstm_rec_kernel(const float* __restrict__ Whh,
                const float* __restrict__ h0,
                const float* __restrict__ c0,
                float* __restrict__ out)
{
    __shared__ float h_s[2][2][2][HDIM];      // [pair][buf][bb][k]
    __shared__ float red_s[2][2][4][2][128];  // [pair][rd][kseg][bb][lr]
    __shared__ alignas(8) unsigned long long mbar[2][2];  // [pair][buf]

    const int tid  = threadIdx.x;
    const int lane = tid & 31;
    const int w    = tid >> 5;
    const int kseg = w >> 2;
    const int lr   = (w & 3) * 32 + lane;

    unsigned rank;
    asm("mov.u32 %0, %%cluster_ctarank;" : "=r"(rank));
    const int b0 = (blockIdx.x >> 3) * 4;           // 4 batches per cluster
    const int R  = ((lr >> 5) << 8) + (int)rank * 32 + (lr & 31);

    // ---- W_hh slice into registers (shared by both pairs) ----
    uint64_t wp[32];
    {
        const float* W = Whh + (size_t)R * HDIM + kseg * 64;
        #pragma unroll
        for (int i = 0; i < 16; i++) {
            float4 v = *(const float4*)(W + 4 * i);
            asm("mov.b64 %0, {%1,%2};" : "=l"(wp[2*i+0]) : "f"(v.x), "f"(v.y));
            asm("mov.b64 %0, {%1,%2};" : "=l"(wp[2*i+1]) : "f"(v.z), "f"(v.w));
        }
    }

    // ---- init h buf0 for both pairs ----
    for (int i = tid; i < 4 * HDIM; i += 512) {
        const int bb = i >> 8, k = i & 255;       // bb 0..3 across pairs
        h_s[bb >> 1][0][bb & 1][k] = h0[(size_t)(b0 + bb) * HDIM + k];
    }

    // ---- owners: warps 0/1 -> pair 0; warps 2/3 -> pair 1 ----
    const int myPair = w >> 1;                     // valid when w < 4
    const int bb = w & 1;
    const int j  = lane;
    const int kglob = (int)rank * 32 + j;
    float c_reg = 0.f, h_last = 0.f;
    if (w < 4)
        c_reg = c0[(size_t)(b0 + 2 * myPair + bb) * HDIM + kglob];

    const uint32_t h_base  = (uint32_t)__cvta_generic_to_shared(&h_s[0][0][0][0]);
    const uint32_t mb_addr = (uint32_t)__cvta_generic_to_shared(&mbar[0][0]);
    const uint32_t mb_delta = mb_addr - h_base;

    if (tid == 0) {
        #pragma unroll
        for (int q = 0; q < 4; q++) {
            asm volatile("mbarrier.init.shared.b64 [%0], %1;" :: "r"(mb_addr + q * 8), "r"(1) : "memory");
            asm volatile("mbarrier.arrive.expect_tx.shared.b64 _, [%0], %1;"
                         :: "r"(mb_addr + q * 8), "r"(TX_PER_BUF) : "memory");
        }
    }
    uint32_t ph[8];
    #pragma unroll
    for (int r = 0; r < 8; r++)
        asm("mapa.shared::cluster.u32 %0, %1, %2;" : "=r"(ph[r]) : "r"(h_base), "r"(r));

    __syncthreads();
    asm volatile("barrier.cluster.arrive.aligned;" ::: "memory");
    asm volatile("barrier.cluster.wait.aligned;" ::: "memory");

    // one phase = one timestep of one pair
    auto phase = [&](int P, int t, int rd, bool dowait, unsigned par, bool dostore) {
        const bool owner = (w < 4) && (myPair == P);

        // owner xg prefetch (hidden under wait + k-loop)
        float xg0 = 0.f, xg1 = 0.f, xg2 = 0.f, xg3 = 0.f;
        if (owner) {
            const float* xp = g_xg + ((size_t)t * BATCH + b0 + 2 * P + bb) * G4 + kglob;
            xg0 = __ldg(xp);
            xg1 = __ldg(xp + 256);
            xg2 = __ldg(xp + 512);
            xg3 = __ldg(xp + 768);
        }

        const uint32_t mb_rd = mb_addr + (uint32_t)(P * 2 + rd) * 8;
        if (dowait) {
            mbar_wait(mb_rd, par);
            if (tid == 0)
                asm volatile("mbarrier.arrive.expect_tx.shared.b64 _, [%0], %1;"
                             :: "r"(mb_rd), "r"(TX_PER_BUF) : "memory");
        }

        // ---- k-loop on pair P's h buffer ----
        const uint32_t a0 = h_base + (uint32_t)(((P * 2 + rd) * 2) * 256 + kseg * 64) * 4;
        const uint32_t a1 = a0 + 1024;
        uint64_t acc0 = 0ull, acc1 = 0ull;
        #pragma unroll
        for (int i = 0; i < 64; i += 4) {
            uint64_t u01, u23, v01, v23;
            asm volatile("ld.shared.v2.u64 {%0,%1}, [%2];"
                         : "=l"(u01), "=l"(u23) : "r"(a0 + i * 4));
            asm volatile("ld.shared.v2.u64 {%0,%1}, [%2];"
                         : "=l"(v01), "=l"(v23) : "r"(a1 + i * 4));
            ffma2(acc0, wp[i / 2 + 0], u01);
            ffma2(acc1, wp[i / 2 + 0], v01);
            ffma2(acc0, wp[i / 2 + 1], u23);
            ffma2(acc1, wp[i / 2 + 1], v23);
        }
        red_s[P][rd][kseg][0][lr] = hsum2(acc0);
        red_s[P][rd][kseg][1][lr] = hsum2(acc1);

        if (!owner) {
            asm volatile("bar.arrive %0, 512;" :: "r"(P + 1) : "memory");
            return;
        }

        asm volatile("bar.sync %0, 512;" :: "r"(P + 1) : "memory");

        float s0 = xg0, s1 = xg1, s2 = xg2, s3 = xg3;
        #pragma unroll
        for (int ks = 0; ks < 4; ks++) {
            s0 += red_s[P][rd][ks][bb][ 0 + j];
            s1 += red_s[P][rd][ks][bb][32 + j];
            s2 += red_s[P][rd][ks][bb][64 + j];
            s3 += red_s[P][rd][ks][bb][96 + j];
        }
        const float ig = __fdividef(1.f, 1.f + __expf(-s0));
        const float fg = __fdividef(1.f, 1.f + __expf(-s1));
        const float gt = 1.f - 2.f * __fdividef(1.f, 1.f + __expf(2.f * s2));
        const float og = __fdividef(1.f, 1.f + __expf(-s3));

        c_reg = fg * c_reg + ig * gt;
        const float h = og * (1.f - 2.f * __fdividef(1.f, 1.f + __expf(2.f * c_reg)));
        h_last = h;

        if (dostore) {
            const float hn = __shfl_down_sync(0xffffffffu, h, 1);
            if ((lane & 1) == 0) {
                uint64_t hp;
                asm("mov.b64 %0, {%1,%2};" : "=l"(hp) : "f"(h), "f"(hn));
                const int wr = rd ^ 1;
                const uint32_t hoff = (uint32_t)((((P * 2 + wr) * 2 + bb) * 256 + kglob) * 4);
                const uint32_t moff = mb_delta + (uint32_t)(P * 2 + wr) * 8;
                #pragma unroll
                for (int r = 0; r < 8; r++) {
                    asm volatile(
                        "st.async.shared::cluster.mbarrier::complete_tx::bytes.b64 [%0], %1, [%2];"
                        :: "r"(ph[r] + hoff), "l"(hp), "r"(ph[r] + moff) : "memory");
                }
            }
        }

        out[((size_t)t * BATCH + b0 + 2 * P + bb) * HDIM + kglob] = h;
    };

    // rd(t) = (t+1)&1; identical schedule per pair, phases interleaved A,B.
    unsigned parA0 = 0, parA1 = 0, parB0 = 0, parB1 = 0;
    phase(0, SEQ - 1, 0, false, 0, true);
    phase(1, SEQ - 1, 0, false, 0, true);
    for (int t = SEQ - 2; t >= 2; t -= 2) {
        phase(0, t,     1, true, parA1, true);
        phase(1, t,     1, true, parB1, true);  parA1 ^= 1; parB1 ^= 1;
        phase(0, t - 1, 0, true, parA0, true);
        phase(1, t - 1, 0, true, parB0, true);  parA0 ^= 1; parB0 ^= 1;
    }
    phase(0, 0, 1, true, parA1, false);
    phase(1, 0, 1, true, parB1, false);

    if (w < 4) {
        float* hT = out + (size_t)SEQ * BATCH * HDIM;
        float* cT = hT + (size_t)BATCH * HDIM;
        hT[(size_t)(b0 + 2 * myPair + bb) * HDIM + kglob] = h_last;
        cT[(size_t)(b0 + 2 * myPair + bb) * HDIM + kglob] = c_reg;
    }
}

// ---------------------------------------------------------------------------
extern "C" void kernel_launch(void* const* d_in, const int* in_sizes, int n_in,
                              void* d_out, int out_size)
{
    (void)in_sizes; (void)n_in; (void)out_size;
    const float* x   = (const float*)d_in[0];
    const float* h0  = (const float*)d_in[1];
    const float* c0  = (const float*)d_in[2];
    const float* Wih = (const float*)d_in[3];
    const float* Whh = (const float*)d_in[4];
    const float* bih = (const float*)d_in[5];
    const float* bhh = (const float*)d_in[6];
    float* out = (float*)d_out;

    dim3 gridP(65536 / BM, G4 / BN);   // (1024, 16)
    xproj_kernel<<<gridP, 256>>>(x, Wih, bih, bhh);

    // 8 clusters x 8 CTAs, 4 batches per cluster (2 interleaved pairs)
    lstm_rec_kernel<<<64, 512>>>(Whh, h0, c0, out);
}

// round 15
// speedup vs baseline: 2.3613x; 2.3613x over previous
#include <cuda_runtime.h>
#include <cstdint>

#define SEQ   2048
#define BATCH 32
#define IDIM  256
#define HDIM  256
#define G4    1024

__device__ float g_xg[SEQ * BATCH * G4];

__device__ __forceinline__ void ffma2(uint64_t& acc, uint64_t a, uint64_t b) {
    asm("fma.rn.f32x2 %0, %1, %2, %0;" : "+l"(acc) : "l"(a), "l"(b));
}
__device__ __forceinline__ float hsum2(uint64_t a) {
    uint32_t lo, hi;
    asm("mov.b64 {%0,%1}, %2;" : "=r"(lo), "=r"(hi) : "l"(a));
    return __uint_as_float(lo) + __uint_as_float(hi);
}

// ---------------------------------------------------------------------------
// Kernel 1 (unchanged from R12): Xg = x @ W_ih^T + b_ih + b_hh
// ---------------------------------------------------------------------------
#define BM 64
#define BN 64
#define BK 32

__global__ __launch_bounds__(256) void xproj_kernel(
    const float* __restrict__ x,
    const float* __restrict__ Wih,
    const float* __restrict__ bih,
    const float* __restrict__ bhh)
{
    __shared__ float As[BK][BM];
    __shared__ float Bs[BK][BN];

    const int tid  = threadIdx.x;
    const int mblk = blockIdx.x;
    const int nblk = blockIdx.y;

    const float* Arow = x   + (size_t)mblk * BM * IDIM;
    const float* Brow = Wih + (size_t)nblk * BN * IDIM;

    const int tx = tid & 15;
    const int ty = tid >> 4;

    uint64_t acc01[4] = {}, acc23[4] = {};

    const int lr  = tid >> 2;
    const int lkq = (tid & 3) * 8;

    for (int k0 = 0; k0 < IDIM; k0 += BK) {
        {
            float4 v0 = *(const float4*)(Arow + lr * IDIM + k0 + lkq);
            float4 v1 = *(const float4*)(Arow + lr * IDIM + k0 + lkq + 4);
            As[lkq + 0][lr] = v0.x; As[lkq + 1][lr] = v0.y;
            As[lkq + 2][lr] = v0.z; As[lkq + 3][lr] = v0.w;
            As[lkq + 4][lr] = v1.x; As[lkq + 5][lr] = v1.y;
            As[lkq + 6][lr] = v1.z; As[lkq + 7][lr] = v1.w;

            float4 w0 = *(const float4*)(Brow + lr * IDIM + k0 + lkq);
            float4 w1 = *(const float4*)(Brow + lr * IDIM + k0 + lkq + 4);
            Bs[lkq + 0][lr] = w0.x; Bs[lkq + 1][lr] = w0.y;
            Bs[lkq + 2][lr] = w0.z; Bs[lkq + 3][lr] = w0.w;
            Bs[lkq + 4][lr] = w1.x; Bs[lkq + 5][lr] = w1.y;
            Bs[lkq + 6][lr] = w1.z; Bs[lkq + 7][lr] = w1.w;
        }
        __syncthreads();

        #pragma unroll
        for (int kk = 0; kk < BK; kk++) {
            float4 av = *(const float4*)&As[kk][ty * 4];
            const uint64_t b01 = *(const uint64_t*)&Bs[kk][tx * 4];
            const uint64_t b23 = *(const uint64_t*)&Bs[kk][tx * 4 + 2];
            float a[4] = {av.x, av.y, av.z, av.w};
            #pragma unroll
            for (int i = 0; i < 4; i++) {
                uint64_t aa;
                asm("mov.b64 %0, {%1,%1};" : "=l"(aa) : "f"(a[i]));
                ffma2(acc01[i], aa, b01);
                ffma2(acc23[i], aa, b23);
            }
        }
        __syncthreads();
    }

    const int mb = mblk * BM + ty * 4;
    const int nb = nblk * BN + tx * 4;
    float bias[4];
    #pragma unroll
    for (int jj = 0; jj < 4; jj++)
        bias[jj] = bih[nb + jj] + bhh[nb + jj];

    #pragma unroll
    for (int i = 0; i < 4; i++) {
        uint32_t lo, hi, lo2, hi2;
        asm("mov.b64 {%0,%1}, %2;" : "=r"(lo), "=r"(hi) : "l"(acc01[i]));
        asm("mov.b64 {%0,%1}, %2;" : "=r"(lo2), "=r"(hi2) : "l"(acc23[i]));
        float4 v;
        v.x = __uint_as_float(lo)  + bias[0];
        v.y = __uint_as_float(hi)  + bias[1];
        v.z = __uint_as_float(lo2) + bias[2];
        v.w = __uint_as_float(hi2) + bias[3];
        *(float4*)&g_xg[(size_t)(mb + i) * G4 + nb] = v;
    }
}

// ---------------------------------------------------------------------------
// Kernel 2: dual-pair recurrence with DEDICATED owner warps.
// 8 clusters x 8 CTAs; cluster owns 4 batches = 2 independent pairs.
// 576 threads: warps 0-15 compute (kseg = w>>2, lr = (w&3)*32+lane),
// warp 16 = owner pair 0, warp 17 = owner pair 1 (lane = unit, both bb).
// Compute stream: waitA kloopA arr1 waitB kloopB arr2 — owners' tails and
// DSMEM hops run concurrently on their own warps, off the compute path.
// Barriers: bar 1 / bar 2, 544 participants each.
// ---------------------------------------------------------------------------
__device__ __forceinline__ void mbar_wait(uint32_t addr, unsigned par) {
    asm volatile(
        "{\n\t"
        ".reg .pred P;\n\t"
        "WAIT_%=:\n\t"
        "mbarrier.try_wait.parity.acquire.cta.shared::cta.b64 P, [%0], %1, 0x989680;\n\t"
        "@P bra DONE_%=;\n\t"
        "bra WAIT_%=;\n\t"
        "DONE_%=:\n\t"
        "}"
        :: "r"(addr), "r"(par) : "memory");
}

#define TX_PER_BUF 2048   // 8 ranks x 64 floats x 4 B per pair-buffer

__global__ void __cluster_dims__(8, 1, 1) __launch_bounds__(576, 1)
lstm_rec_kernel(const float* __restrict__ Whh,
                const float* __restrict__ h0,
                const float* __restrict__ c0,
                float* __restrict__ out)
{
    __shared__ float h_s[2][2][2][HDIM];      // [pair][buf][bb][k]
    __shared__ float red_s[2][2][4][2][128];  // [pair][rd][kseg][bb][lr]
    __shared__ alignas(8) unsigned long long mbar[4];  // [pair*2 + buf]

    const int tid  = threadIdx.x;
    const int lane = tid & 31;
    const int w    = tid >> 5;

    unsigned rank;
    asm("mov.u32 %0, %%cluster_ctarank;" : "=r"(rank));
    const int b0 = (blockIdx.x >> 3) * 4;

    const uint32_t h_base  = (uint32_t)__cvta_generic_to_shared(&h_s[0][0][0][0]);
    const uint32_t mb_addr = (uint32_t)__cvta_generic_to_shared(&mbar[0]);

    // ---- shared init (all 576 threads) ----
    for (int i = tid; i < 4 * HDIM; i += 576) {
        const int bb = i >> 8, k = i & 255;
        h_s[bb >> 1][0][bb & 1][k] = h0[(size_t)(b0 + bb) * HDIM + k];
    }
    if (tid == 0) {
        #pragma unroll
        for (int q = 0; q < 4; q++) {
            asm volatile("mbarrier.init.shared.b64 [%0], %1;" :: "r"(mb_addr + q * 8), "r"(1) : "memory");
            asm volatile("mbarrier.arrive.expect_tx.shared.b64 _, [%0], %1;"
                         :: "r"(mb_addr + q * 8), "r"(TX_PER_BUF) : "memory");
        }
    }
    __syncthreads();
    asm volatile("barrier.cluster.arrive.aligned;" ::: "memory");
    asm volatile("barrier.cluster.wait.aligned;" ::: "memory");

    if (tid < 512) {
        // =================== COMPUTE WARPS ===================
        const int kseg = w >> 2;
        const int lr   = (w & 3) * 32 + lane;
        const int R    = ((lr >> 5) << 8) + (int)rank * 32 + (lr & 31);

        uint64_t wp[32];
        {
            const float* W = Whh + (size_t)R * HDIM + kseg * 64;
            #pragma unroll
            for (int i = 0; i < 16; i++) {
                float4 v = *(const float4*)(W + 4 * i);
                asm("mov.b64 %0, {%1,%2};" : "=l"(wp[2*i+0]) : "f"(v.x), "f"(v.y));
                asm("mov.b64 %0, {%1,%2};" : "=l"(wp[2*i+1]) : "f"(v.z), "f"(v.w));
            }
        }

        auto cphase = [&](int P, int rd, bool dowait, unsigned par) {
            const uint32_t mb_rd = mb_addr + (uint32_t)(P * 2 + rd) * 8;
            if (dowait) {
                mbar_wait(mb_rd, par);
                if (tid == 0)
                    asm volatile("mbarrier.arrive.expect_tx.shared.b64 _, [%0], %1;"
                                 :: "r"(mb_rd), "r"(TX_PER_BUF) : "memory");
            }
            const uint32_t a0 = h_base + (uint32_t)(((P * 2 + rd) * 2) * 256 + kseg * 64) * 4;
            const uint32_t a1 = a0 + 1024;
            uint64_t acc0 = 0ull, acc1 = 0ull;
            #pragma unroll
            for (int i = 0; i < 64; i += 4) {
                uint64_t u01, u23, v01, v23;
                asm volatile("ld.shared.v2.u64 {%0,%1}, [%2];"
                             : "=l"(u01), "=l"(u23) : "r"(a0 + i * 4));
                asm volatile("ld.shared.v2.u64 {%0,%1}, [%2];"
                             : "=l"(v01), "=l"(v23) : "r"(a1 + i * 4));
                ffma2(acc0, wp[i / 2 + 0], u01);
                ffma2(acc1, wp[i / 2 + 0], v01);
                ffma2(acc0, wp[i / 2 + 1], u23);
                ffma2(acc1, wp[i / 2 + 1], v23);
            }
            red_s[P][rd][kseg][0][lr] = hsum2(acc0);
            red_s[P][rd][kseg][1][lr] = hsum2(acc1);
            if (P == 0)
                asm volatile("bar.arrive 1, 544;" ::: "memory");
            else
                asm volatile("bar.arrive 2, 544;" ::: "memory");
        };

        unsigned parA[2] = {0, 0}, parB[2] = {0, 0};
        cphase(0, 0, false, 0);
        cphase(1, 0, false, 0);
        for (int t = SEQ - 2; t >= 2; t -= 2) {
            cphase(0, 1, true, parA[1]);
            cphase(1, 1, true, parB[1]);  parA[1] ^= 1; parB[1] ^= 1;
            cphase(0, 0, true, parA[0]);
            cphase(1, 0, true, parB[0]);  parA[0] ^= 1; parB[0] ^= 1;
        }
        cphase(0, 1, true, parA[1]);
        cphase(1, 1, true, parB[1]);
    } else {
        // =================== OWNER WARPS ===================
        const int P = (tid >= 544) ? 1 : 0;
        const int j = lane;
        const int kglob = (int)rank * 32 + j;
        const uint32_t mb_delta = mb_addr - h_base;

        uint32_t ph[8];
        #pragma unroll
        for (int r = 0; r < 8; r++)
            asm("mapa.shared::cluster.u32 %0, %1, %2;" : "=r"(ph[r]) : "r"(h_base), "r"(r));

        float c0r = c0[(size_t)(b0 + 2 * P + 0) * HDIM + kglob];
        float c1r = c0[(size_t)(b0 + 2 * P + 1) * HDIM + kglob];
        float h0r = 0.f, h1r = 0.f;

        for (int t = SEQ - 1; t >= 0; t--) {
            const int rd = (t + 1) & 1;
            const bool dostore = (t > 0);

            // xg prefetch (covered by the bar wait below)
            const float* xp0 = g_xg + ((size_t)t * BATCH + b0 + 2 * P + 0) * G4 + kglob;
            const float* xp1 = g_xg + ((size_t)t * BATCH + b0 + 2 * P + 1) * G4 + kglob;
            const float a00 = __ldg(xp0),       a01 = __ldg(xp0 + 256);
            const float a02 = __ldg(xp0 + 512), a03 = __ldg(xp0 + 768);
            const float a10 = __ldg(xp1),       a11 = __ldg(xp1 + 256);
            const float a12 = __ldg(xp1 + 512), a13 = __ldg(xp1 + 768);

            if (P == 0)
                asm volatile("bar.sync 1, 544;" ::: "memory");
            else
                asm volatile("bar.sync 2, 544;" ::: "memory");

            float s00 = a00, s01 = a01, s02 = a02, s03 = a03;
            float s10 = a10, s11 = a11, s12 = a12, s13 = a13;
            #pragma unroll
            for (int ks = 0; ks < 4; ks++) {
                const float* rp0 = &red_s[P][rd][ks][0][0];
                const float* rp1 = &red_s[P][rd][ks][1][0];
                s00 += rp0[ 0 + j]; s01 += rp0[32 + j];
                s02 += rp0[64 + j]; s03 += rp0[96 + j];
                s10 += rp1[ 0 + j]; s11 += rp1[32 + j];
                s12 += rp1[64 + j]; s13 += rp1[96 + j];
            }

            const float ig0 = __fdividef(1.f, 1.f + __expf(-s00));
            const float fg0 = __fdividef(1.f, 1.f + __expf(-s01));
            const float gt0 = 1.f - 2.f * __fdividef(1.f, 1.f + __expf(2.f * s02));
            const float og0 = __fdividef(1.f, 1.f + __expf(-s03));
            const float ig1 = __fdividef(1.f, 1.f + __expf(-s10));
            const float fg1 = __fdividef(1.f, 1.f + __expf(-s11));
            const float gt1 = 1.f - 2.f * __fdividef(1.f, 1.f + __expf(2.f * s12));
            const float og1 = __fdividef(1.f, 1.f + __expf(-s13));

            c0r = fg0 * c0r + ig0 * gt0;
            c1r = fg1 * c1r + ig1 * gt1;
            const float h0v = og0 * (1.f - 2.f * __fdividef(1.f, 1.f + __expf(2.f * c0r)));
            const float h1v = og1 * (1.f - 2.f * __fdividef(1.f, 1.f + __expf(2.f * c1r)));
            h0r = h0v; h1r = h1v;

            if (dostore) {
                const int wr = rd ^ 1;
                const float hn0 = __shfl_down_sync(0xffffffffu, h0v, 1);
                const float hn1 = __shfl_down_sync(0xffffffffu, h1v, 1);
                if ((lane & 1) == 0) {
                    uint64_t p0, p1;
                    asm("mov.b64 %0, {%1,%2};" : "=l"(p0) : "f"(h0v), "f"(hn0));
                    asm("mov.b64 %0, {%1,%2};" : "=l"(p1) : "f"(h1v), "f"(hn1));
                    const uint32_t o0 = (uint32_t)((((P * 2 + wr) * 2 + 0) * 256 + kglob) * 4);
                    const uint32_t o1 = (uint32_t)((((P * 2 + wr) * 2 + 1) * 256 + kglob) * 4);
                    const uint32_t mo = mb_delta + (uint32_t)(P * 2 + wr) * 8;
                    #pragma unroll
                    for (int r = 0; r < 8; r++) {
                        asm volatile(
                            "st.async.shared::cluster.mbarrier::complete_tx::bytes.b64 [%0], %1, [%2];"
                            :: "r"(ph[r] + o0), "l"(p0), "r"(ph[r] + mo) : "memory");
                        asm volatile(
                            "st.async.shared::cluster.mbarrier::complete_tx::bytes.b64 [%0], %1, [%2];"
                            :: "r"(ph[r] + o1), "l"(p1), "r"(ph[r] + mo) : "memory");
                    }
                }
            }

            out[((size_t)t * BATCH + b0 + 2 * P + 0) * HDIM + kglob] = h0v;
            out[((size_t)t * BATCH + b0 + 2 * P + 1) * HDIM + kglob] = h1v;
        }

        float* hT = out + (size_t)SEQ * BATCH * HDIM;
        float* cT = hT + (size_t)BATCH * HDIM;
        hT[(size_t)(b0 + 2 * P + 0) * HDIM + kglob] = h0r;
        hT[(size_t)(b0 + 2 * P + 1) * HDIM + kglob] = h1r;
        cT[(size_t)(b0 + 2 * P + 0) * HDIM + kglob] = c0r;
        cT[(size_t)(b0 + 2 * P + 1) * HDIM + kglob] = c1r;
    }
}

// ---------------------------------------------------------------------------
extern "C" void kernel_launch(void* const* d_in, const int* in_sizes, int n_in,
                              void* d_out, int out_size)
{
    (void)in_sizes; (void)n_in; (void)out_size;
    const float* x   = (const float*)d_in[0];
    const float* h0  = (const float*)d_in[1];
    const float* c0  = (const float*)d_in[2];
    const float* Wih = (const float*)d_in[3];
    const float* Whh = (const float*)d_in[4];
    const float* bih = (const float*)d_in[5];
    const float* bhh = (const float*)d_in[6];
    float* out = (float*)d_out;

    dim3 gridP(65536 / BM, G4 / BN);   // (1024, 16)
    xproj_kernel<<<gridP, 256>>>(x, Wih, bih, bhh);

    // 8 clusters x 8 CTAs, 4 batches per cluster (2 pairs, dedicated owners)
    lstm_rec_kernel<<<64, 576>>>(Whh, h0, c0, out);
}